// round 1
// baseline (speedup 1.0000x reference)
#include <cuda_runtime.h>
#include <math.h>

#define E_    1024
#define H_    16
#define DH    64
#define B_    4
#define N_    1024
#define ROWS  (B_ * N_)      // 4096
#define FF    (4 * E_)       // 4096
#define MAXLEN 512

// ---------------- scratch (no allocs allowed) ----------------
__device__ float g_xn[ROWS * E_];        // LN1 output
__device__ float g_qkv[ROWS * 3 * E_];   // QKV projections
__device__ float g_o[ROWS * E_];         // attention output (merged heads)
__device__ float g_xm[ROWS * E_];        // LN2 output
__device__ float g_hbuf[ROWS * FF];      // FFN hidden

// ---------------- LayerNorm ----------------
// one block per row, 256 threads, 4 elems/thread (E=1024)
__global__ void ln_kernel(const float* __restrict__ x, const float* __restrict__ g,
                          const float* __restrict__ bt, float* __restrict__ out) {
    int row = blockIdx.x;
    int tid = threadIdx.x;
    const float4* xr = (const float4*)(x + (size_t)row * E_);
    float4 v = xr[tid];
    float s  = v.x + v.y + v.z + v.w;
    float s2 = v.x*v.x + v.y*v.y + v.z*v.z + v.w*v.w;
    #pragma unroll
    for (int o = 16; o; o >>= 1) {
        s  += __shfl_xor_sync(0xffffffffu, s,  o);
        s2 += __shfl_xor_sync(0xffffffffu, s2, o);
    }
    __shared__ float ws[8], ws2[8];
    int w = tid >> 5;
    if ((tid & 31) == 0) { ws[w] = s; ws2[w] = s2; }
    __syncthreads();
    if (tid < 32) {
        float a  = (tid < 8) ? ws[tid]  : 0.f;
        float a2 = (tid < 8) ? ws2[tid] : 0.f;
        #pragma unroll
        for (int o = 4; o; o >>= 1) {
            a  += __shfl_xor_sync(0xffffffffu, a,  o);
            a2 += __shfl_xor_sync(0xffffffffu, a2, o);
        }
        if (tid == 0) {
            float mu  = a / (float)E_;
            float var = a2 / (float)E_ - mu * mu;
            ws[0]  = mu;
            ws2[0] = rsqrtf(var + 1e-5f);
        }
    }
    __syncthreads();
    float mu = ws[0], rstd = ws2[0];
    float4 gv = ((const float4*)g)[tid];
    float4 bv = ((const float4*)bt)[tid];
    float4 ov;
    ov.x = (v.x - mu) * rstd * gv.x + bv.x;
    ov.y = (v.y - mu) * rstd * gv.y + bv.y;
    ov.z = (v.z - mu) * rstd * gv.z + bv.z;
    ov.w = (v.w - mu) * rstd * gv.w + bv.w;
    ((float4*)(out + (size_t)row * E_))[tid] = ov;
}

// ---------------- GEMM: C[M,N] = A[M,K] @ W[N,K]^T + bias (+res) (relu?) ----------
// 128x128 tile, BK=8, 256 threads, 8x8 micro-tile
__global__ void __launch_bounds__(256, 2)
gemm_kernel(const float* __restrict__ A, const float* __restrict__ W,
            const float* __restrict__ bias, const float* __restrict__ res,
            float* __restrict__ C, int M, int Nn, int K, int relu) {
    __shared__ float As[8][128];
    __shared__ float Ws[8][128];
    int bm = blockIdx.y * 128, bn = blockIdx.x * 128;
    int tid = threadIdx.x;
    int lr = tid >> 1;           // 0..127
    int lc = (tid & 1) * 4;      // 0 or 4
    const float* Aptr = A + (size_t)(bm + lr) * K + lc;
    const float* Wptr = W + (size_t)(bn + lr) * K + lc;
    int tx = tid & 15, ty = tid >> 4;

    float acc[8][8];
    #pragma unroll
    for (int i = 0; i < 8; i++)
        #pragma unroll
        for (int j = 0; j < 8; j++) acc[i][j] = 0.f;

    for (int k0 = 0; k0 < K; k0 += 8) {
        float4 av = *(const float4*)(Aptr + k0);
        float4 wv = *(const float4*)(Wptr + k0);
        __syncthreads();
        As[lc + 0][lr] = av.x; As[lc + 1][lr] = av.y;
        As[lc + 2][lr] = av.z; As[lc + 3][lr] = av.w;
        Ws[lc + 0][lr] = wv.x; Ws[lc + 1][lr] = wv.y;
        Ws[lc + 2][lr] = wv.z; Ws[lc + 3][lr] = wv.w;
        __syncthreads();
        #pragma unroll
        for (int kk = 0; kk < 8; kk++) {
            float af[8], bf[8];
            *(float4*)(af)     = *(const float4*)&As[kk][ty * 8];
            *(float4*)(af + 4) = *(const float4*)&As[kk][ty * 8 + 4];
            *(float4*)(bf)     = *(const float4*)&Ws[kk][tx * 8];
            *(float4*)(bf + 4) = *(const float4*)&Ws[kk][tx * 8 + 4];
            #pragma unroll
            for (int i = 0; i < 8; i++)
                #pragma unroll
                for (int j = 0; j < 8; j++)
                    acc[i][j] += af[i] * bf[j];
        }
    }
    // epilogue
    #pragma unroll
    for (int i = 0; i < 8; i++) {
        int row = bm + ty * 8 + i;
        float* crow = C + (size_t)row * Nn + bn + tx * 8;
        const float* rrow = res ? (res + (size_t)row * Nn + bn + tx * 8) : nullptr;
        const float* brow = bias + bn + tx * 8;
        #pragma unroll
        for (int j = 0; j < 8; j++) {
            float v = acc[i][j] + brow[j];
            if (relu) v = fmaxf(v, 0.f);
            if (rrow) v += rrow[j];
            crow[j] = v;
        }
    }
}

// ---------------- Windowed attention (flash-style, online softmax) --------------
// bias(i,j) = rel_pos[h, i-j] if 0<=i-j<512 else -inf  => causal + 512 window
// block: (qt, h, b); 64 query rows, 256 threads (4 threads/row), key tiles of 32
__global__ void __launch_bounds__(256)
attn_kernel(const float* __restrict__ qkv, const float* __restrict__ rel_pos,
            float* __restrict__ o) {
    __shared__ float Qs[64][68];   // [qrow][d]
    __shared__ float Kt[64][33];   // [d][k]  (transposed, conflict-free pitch)
    __shared__ float Vs[32][68];   // [k][d]
    __shared__ float Ss[64][33];   // [qrow][k] probabilities

    int qt = blockIdx.x, h = blockIdx.y, b = blockIdx.z;
    int tid = threadIdx.x;
    int qs = qt * 64;
    const float* base = qkv + (size_t)b * N_ * 3 * E_;

    // load Q tile
    {
        int row = tid >> 2;
        int c = (tid & 3) * 16;
        const float* qp = base + (size_t)(qs + row) * 3 * E_ + h * DH;
        #pragma unroll
        for (int i = 0; i < 4; i++)
            *(float4*)&Qs[row][c + i * 4] = *(const float4*)(qp + c + i * 4);
    }

    int qrow = tid >> 2;
    int quarter = tid & 3;
    int i_glob = qs + qrow;
    float m_old = -INFINITY;
    float l = 0.f;
    float acc[16];
    #pragma unroll
    for (int i = 0; i < 16; i++) acc[i] = 0.f;

    int kt_lo = max(0, qs - (MAXLEN - 1)) >> 5;
    int kt_hi = (qs + 63) >> 5;
    const float* rp = rel_pos + h * MAXLEN;
    int kb = quarter * 8;
    int dbase = quarter * 16;

    for (int kt = kt_lo; kt <= kt_hi; kt++) {
        int ks0 = kt * 32;
        __syncthreads();  // protect Kt/Vs/Ss reuse
        {
            int j = tid >> 3;            // 0..31
            int d0 = (tid & 7) * 8;      // 0..56
            const float* kp = base + (size_t)(ks0 + j) * 3 * E_ + E_ + h * DH + d0;
            const float* vp = base + (size_t)(ks0 + j) * 3 * E_ + 2 * E_ + h * DH + d0;
            float4 k0v = *(const float4*)kp;
            float4 k1v = *(const float4*)(kp + 4);
            Kt[d0 + 0][j] = k0v.x; Kt[d0 + 1][j] = k0v.y;
            Kt[d0 + 2][j] = k0v.z; Kt[d0 + 3][j] = k0v.w;
            Kt[d0 + 4][j] = k1v.x; Kt[d0 + 5][j] = k1v.y;
            Kt[d0 + 6][j] = k1v.z; Kt[d0 + 7][j] = k1v.w;
            *(float4*)&Vs[j][d0]     = *(const float4*)vp;
            *(float4*)&Vs[j][d0 + 4] = *(const float4*)(vp + 4);
        }
        __syncthreads();

        // S = Q K^T for this thread's 8 keys
        float s[8];
        #pragma unroll
        for (int i = 0; i < 8; i++) s[i] = 0.f;
        for (int d = 0; d < 64; d += 4) {
            float4 q4 = *(const float4*)&Qs[qrow][d];
            float qd0 = q4.x, qd1 = q4.y, qd2 = q4.z, qd3 = q4.w;
            #pragma unroll
            for (int kk = 0; kk < 8; kk++) {
                s[kk] += qd0 * Kt[d + 0][kb + kk];
                s[kk] += qd1 * Kt[d + 1][kb + kk];
                s[kk] += qd2 * Kt[d + 2][kb + kk];
                s[kk] += qd3 * Kt[d + 3][kb + kk];
            }
        }
        // scale + relative-position bias + window mask
        float m_t = -INFINITY;
        #pragma unroll
        for (int kk = 0; kk < 8; kk++) {
            int j = ks0 + kb + kk;
            int rel = i_glob - j;
            if (rel >= 0 && rel < MAXLEN)
                s[kk] = s[kk] * 0.125f + __ldg(rp + rel);
            else
                s[kk] = -INFINITY;
            m_t = fmaxf(m_t, s[kk]);
        }
        // row max across the 4 lanes covering this row (lanes 4q..4q+3)
        m_t = fmaxf(m_t, __shfl_xor_sync(0xffffffffu, m_t, 1));
        m_t = fmaxf(m_t, __shfl_xor_sync(0xffffffffu, m_t, 2));
        float m_new = fmaxf(m_old, m_t);
        if (m_new == -INFINITY) {
            // whole tile masked for this row: contribute nothing
            #pragma unroll
            for (int kk = 0; kk < 8; kk++) Ss[qrow][kb + kk] = 0.f;
        } else {
            float factor = __expf(m_old - m_new);   // m_old=-inf -> 0
            float psum = 0.f;
            #pragma unroll
            for (int kk = 0; kk < 8; kk++) {
                float p = (s[kk] == -INFINITY) ? 0.f : __expf(s[kk] - m_new);
                Ss[qrow][kb + kk] = p;
                psum += p;
            }
            l = l * factor + psum;
            #pragma unroll
            for (int i = 0; i < 16; i++) acc[i] *= factor;
            m_old = m_new;
        }
        __syncthreads();
        // acc += P V  (this thread's 16 d-columns)
        #pragma unroll 4
        for (int k = 0; k < 32; k++) {
            float p = Ss[qrow][k];
            #pragma unroll
            for (int i = 0; i < 16; i += 4) {
                float4 v4 = *(const float4*)&Vs[k][dbase + i];
                acc[i + 0] += p * v4.x;
                acc[i + 1] += p * v4.y;
                acc[i + 2] += p * v4.z;
                acc[i + 3] += p * v4.w;
            }
        }
    }
    // combine l across the 4 lanes of this row
    float lt = l;
    lt += __shfl_xor_sync(0xffffffffu, lt, 1);
    lt += __shfl_xor_sync(0xffffffffu, lt, 2);
    float inv = 1.f / lt;   // diagonal key always valid -> lt > 0
    float* op = o + ((size_t)(b * N_ + i_glob)) * E_ + h * DH + dbase;
    #pragma unroll
    for (int i = 0; i < 16; i++) op[i] = acc[i] * inv;
}

// ---------------- driver ----------------
extern "C" void kernel_launch(void* const* d_in, const int* in_sizes, int n_in,
                              void* d_out, int out_size) {
    const float* x         = (const float*)d_in[0];
    const float* rel_pos   = (const float*)d_in[1];
    const float* in_proj_w = (const float*)d_in[2];
    const float* in_proj_b = (const float*)d_in[3];
    const float* out_w     = (const float*)d_in[4];
    const float* out_b     = (const float*)d_in[5];
    const float* w1        = (const float*)d_in[6];
    const float* b1        = (const float*)d_in[7];
    const float* w2        = (const float*)d_in[8];
    const float* b2        = (const float*)d_in[9];
    const float* ln1_g     = (const float*)d_in[10];
    const float* ln1_b     = (const float*)d_in[11];
    const float* ln2_g     = (const float*)d_in[12];
    const float* ln2_b     = (const float*)d_in[13];
    float* out = (float*)d_out;

    float *xn, *qkv, *o, *xm, *hbuf;
    cudaGetSymbolAddress((void**)&xn,   g_xn);
    cudaGetSymbolAddress((void**)&qkv,  g_qkv);
    cudaGetSymbolAddress((void**)&o,    g_o);
    cudaGetSymbolAddress((void**)&xm,   g_xm);
    cudaGetSymbolAddress((void**)&hbuf, g_hbuf);

    // 1) LN1
    ln_kernel<<<ROWS, 256>>>(x, ln1_g, ln1_b, xn);
    // 2) QKV = xn @ in_proj_w^T + b       [4096, 3072]
    gemm_kernel<<<dim3(3 * E_ / 128, ROWS / 128), 256>>>(
        xn, in_proj_w, in_proj_b, nullptr, qkv, ROWS, 3 * E_, E_, 0);
    // 3) windowed attention -> o          [4096, 1024]
    attn_kernel<<<dim3(N_ / 64, H_, B_), 256>>>(qkv, rel_pos, o);
    // 4) x2 = x + o @ out_w^T + out_b  -> d_out
    gemm_kernel<<<dim3(E_ / 128, ROWS / 128), 256>>>(
        o, out_w, out_b, x, out, ROWS, E_, E_, 0);
    // 5) LN2
    ln_kernel<<<ROWS, 256>>>(out, ln2_g, ln2_b, xm);
    // 6) h = relu(xm @ w1^T + b1)         [4096, 4096]
    gemm_kernel<<<dim3(FF / 128, ROWS / 128), 256>>>(
        xm, w1, b1, nullptr, hbuf, ROWS, FF, E_, 1);
    // 7) out = x2 + h @ w2^T + b2
    gemm_kernel<<<dim3(E_ / 128, ROWS / 128), 256>>>(
        hbuf, w2, b2, out, out, ROWS, E_, FF, 0);
}

// round 3
// speedup vs baseline: 2.2779x; 2.2779x over previous
#include <cuda_runtime.h>
#include <math.h>
#include <stdint.h>

#define E_    1024
#define H_    16
#define DH    64
#define B_    4
#define N_    1024
#define ROWS  (B_ * N_)      // 4096
#define FF    (4 * E_)       // 4096
#define MAXLEN 512

// ---------------- scratch (no allocs allowed) ----------------
__device__ float g_xn[ROWS * E_];        // LN1 output
__device__ float g_qkv[ROWS * 3 * E_];   // QKV projections
__device__ float g_o[ROWS * E_];         // attention output (merged heads)
__device__ float g_xm[ROWS * E_];        // LN2 output
__device__ float g_hbuf[ROWS * FF];      // FFN hidden

__device__ __forceinline__ uint32_t cvt_tf32(float f) {
    uint32_t r;
    asm("cvt.rna.tf32.f32 %0, %1;" : "=r"(r) : "f"(f));
    return r;
}

// ---------------- LayerNorm ----------------
__global__ void ln_kernel(const float* __restrict__ x, const float* __restrict__ g,
                          const float* __restrict__ bt, float* __restrict__ out) {
    int row = blockIdx.x;
    int tid = threadIdx.x;
    const float4* xr = (const float4*)(x + (size_t)row * E_);
    float4 v = xr[tid];
    float s  = v.x + v.y + v.z + v.w;
    float s2 = v.x*v.x + v.y*v.y + v.z*v.z + v.w*v.w;
    #pragma unroll
    for (int o = 16; o; o >>= 1) {
        s  += __shfl_xor_sync(0xffffffffu, s,  o);
        s2 += __shfl_xor_sync(0xffffffffu, s2, o);
    }
    __shared__ float ws[8], ws2[8];
    int w = tid >> 5;
    if ((tid & 31) == 0) { ws[w] = s; ws2[w] = s2; }
    __syncthreads();
    if (tid < 32) {
        float a  = (tid < 8) ? ws[tid]  : 0.f;
        float a2 = (tid < 8) ? ws2[tid] : 0.f;
        #pragma unroll
        for (int o = 4; o; o >>= 1) {
            a  += __shfl_xor_sync(0xffffffffu, a,  o);
            a2 += __shfl_xor_sync(0xffffffffu, a2, o);
        }
        if (tid == 0) {
            float mu  = a / (float)E_;
            float var = a2 / (float)E_ - mu * mu;
            ws[0]  = mu;
            ws2[0] = rsqrtf(var + 1e-5f);
        }
    }
    __syncthreads();
    float mu = ws[0], rstd = ws2[0];
    float4 gv = ((const float4*)g)[tid];
    float4 bv = ((const float4*)bt)[tid];
    float4 ov;
    ov.x = (v.x - mu) * rstd * gv.x + bv.x;
    ov.y = (v.y - mu) * rstd * gv.y + bv.y;
    ov.z = (v.z - mu) * rstd * gv.z + bv.z;
    ov.w = (v.w - mu) * rstd * gv.w + bv.w;
    ((float4*)(out + (size_t)row * E_))[tid] = ov;
}

// ---------------- tf32 mma.sync GEMM: C = A[M,K] @ W[N,K]^T (+bias)(+res)(relu) ----
// 128x128 block tile, 4 warps (2x2), 64x64 warp tile, BK=16, double buffered.
#define BK  16
#define SST 20   // smem row stride in floats (conflict-free: 20g%32 spans all banks)

__device__ __forceinline__ void mma_tf32(float* c, const uint32_t* a, const uint32_t* b) {
    asm volatile(
        "mma.sync.aligned.m16n8k8.row.col.f32.tf32.tf32.f32 "
        "{%0,%1,%2,%3}, {%4,%5,%6,%7}, {%8,%9}, {%0,%1,%2,%3};"
        : "+f"(c[0]), "+f"(c[1]), "+f"(c[2]), "+f"(c[3])
        : "r"(a[0]), "r"(a[1]), "r"(a[2]), "r"(a[3]), "r"(b[0]), "r"(b[1]));
}

__global__ void __launch_bounds__(128)
gemm_tc(const float* __restrict__ A, const float* __restrict__ W,
        const float* __restrict__ bias, const float* __restrict__ res,
        float* __restrict__ C, int M, int Nn, int K, int relu) {
    __shared__ uint32_t SA[2][128 * SST];
    __shared__ uint32_t SB[2][128 * SST];

    int tid = threadIdx.x;
    int wid = tid >> 5, lane = tid & 31;
    int g = lane >> 2, t = lane & 3;
    int wm = wid >> 1, wn = wid & 1;              // 2x2 warp grid
    int bm = blockIdx.y * 128, bn = blockIdx.x * 128;

    // gmem load mapping: 4 rows-chunks, row = (tid>>2)+32*i, col4 = tid&3
    int lrow = tid >> 2, lc4 = tid & 3;
    const float* Ag = A + (size_t)(bm + lrow) * K + lc4 * 4;
    const float* Wg = W + (size_t)(bn + lrow) * K + lc4 * 4;

    float acc[4][8][4];
    #pragma unroll
    for (int i = 0; i < 4; i++)
        #pragma unroll
        for (int j = 0; j < 8; j++)
            #pragma unroll
            for (int v = 0; v < 4; v++) acc[i][j][v] = 0.f;

    int S = K / BK;
    float4 pa[4], pb[4];
    #pragma unroll
    for (int i = 0; i < 4; i++) {
        pa[i] = *(const float4*)(Ag + (size_t)(i * 32) * K);
        pb[i] = *(const float4*)(Wg + (size_t)(i * 32) * K);
    }
    #pragma unroll
    for (int i = 0; i < 4; i++) {
        uint32_t* da = &SA[0][(lrow + i * 32) * SST + lc4 * 4];
        uint32_t* db = &SB[0][(lrow + i * 32) * SST + lc4 * 4];
        da[0] = cvt_tf32(pa[i].x); da[1] = cvt_tf32(pa[i].y);
        da[2] = cvt_tf32(pa[i].z); da[3] = cvt_tf32(pa[i].w);
        db[0] = cvt_tf32(pb[i].x); db[1] = cvt_tf32(pb[i].y);
        db[2] = cvt_tf32(pb[i].z); db[3] = cvt_tf32(pb[i].w);
    }
    __syncthreads();

    for (int s = 0; s < S; s++) {
        int cur = s & 1;
        if (s + 1 < S) {
            const float* Ag2 = Ag + (size_t)(s + 1) * BK;
            const float* Wg2 = Wg + (size_t)(s + 1) * BK;
            #pragma unroll
            for (int i = 0; i < 4; i++) {
                pa[i] = *(const float4*)(Ag2 + (size_t)(i * 32) * K);
                pb[i] = *(const float4*)(Wg2 + (size_t)(i * 32) * K);
            }
        }
        // two k-steps of 8
        #pragma unroll
        for (int ks = 0; ks < 2; ks++) {
            int ko = ks * 8 + t;
            uint32_t af[4][4];
            #pragma unroll
            for (int mi = 0; mi < 4; mi++) {
                int r0 = wm * 64 + mi * 16 + g;
                af[mi][0] = SA[cur][r0 * SST + ko];
                af[mi][1] = SA[cur][(r0 + 8) * SST + ko];
                af[mi][2] = SA[cur][r0 * SST + ko + 4];
                af[mi][3] = SA[cur][(r0 + 8) * SST + ko + 4];
            }
            uint32_t bf[8][2];
            #pragma unroll
            for (int ni = 0; ni < 8; ni++) {
                int rn = wn * 64 + ni * 8 + g;
                bf[ni][0] = SB[cur][rn * SST + ko];
                bf[ni][1] = SB[cur][rn * SST + ko + 4];
            }
            #pragma unroll
            for (int mi = 0; mi < 4; mi++)
                #pragma unroll
                for (int ni = 0; ni < 8; ni++)
                    mma_tf32(acc[mi][ni], af[mi], bf[ni]);
        }
        if (s + 1 < S) {
            int nxt = cur ^ 1;
            #pragma unroll
            for (int i = 0; i < 4; i++) {
                uint32_t* da = &SA[nxt][(lrow + i * 32) * SST + lc4 * 4];
                uint32_t* db = &SB[nxt][(lrow + i * 32) * SST + lc4 * 4];
                da[0] = cvt_tf32(pa[i].x); da[1] = cvt_tf32(pa[i].y);
                da[2] = cvt_tf32(pa[i].z); da[3] = cvt_tf32(pa[i].w);
                db[0] = cvt_tf32(pb[i].x); db[1] = cvt_tf32(pb[i].y);
                db[2] = cvt_tf32(pb[i].z); db[3] = cvt_tf32(pb[i].w);
            }
            __syncthreads();
        }
    }

    // epilogue: c0=(g,2t) c1=(g,2t+1) c2=(g+8,2t) c3=(g+8,2t+1)
    #pragma unroll
    for (int mi = 0; mi < 4; mi++) {
        int r0 = bm + wm * 64 + mi * 16 + g;
        #pragma unroll
        for (int half = 0; half < 2; half++) {
            int row = r0 + half * 8;
            float* crow = C + (size_t)row * Nn + bn + wn * 64;
            const float* rrow = res ? res + (size_t)row * Nn + bn + wn * 64 : nullptr;
            const float* brow = bias + bn + wn * 64;
            #pragma unroll
            for (int ni = 0; ni < 8; ni++) {
                int col = ni * 8 + 2 * t;
                float v0 = acc[mi][ni][half * 2 + 0] + brow[col];
                float v1 = acc[mi][ni][half * 2 + 1] + brow[col + 1];
                if (relu) { v0 = fmaxf(v0, 0.f); v1 = fmaxf(v1, 0.f); }
                if (rrow) { v0 += rrow[col]; v1 += rrow[col + 1]; }
                float2 o2 = make_float2(v0, v1);
                *(float2*)(crow + col) = o2;
            }
        }
    }
}

// ---------------- Windowed attention (flash-style, online softmax) --------------
__global__ void __launch_bounds__(256)
attn_kernel(const float* __restrict__ qkv, const float* __restrict__ rel_pos,
            float* __restrict__ o) {
    __shared__ float Qs[64][68];
    __shared__ float Kt[64][33];
    __shared__ float Vs[32][68];
    __shared__ float Ss[64][33];

    int qt = blockIdx.x, h = blockIdx.y, b = blockIdx.z;
    int tid = threadIdx.x;
    int qs = qt * 64;
    const float* base = qkv + (size_t)b * N_ * 3 * E_;

    {
        int row = tid >> 2;
        int c = (tid & 3) * 16;
        const float* qp = base + (size_t)(qs + row) * 3 * E_ + h * DH;
        #pragma unroll
        for (int i = 0; i < 4; i++)
            *(float4*)&Qs[row][c + i * 4] = *(const float4*)(qp + c + i * 4);
    }

    int qrow = tid >> 2;
    int quarter = tid & 3;
    int i_glob = qs + qrow;
    float m_old = -INFINITY;
    float l = 0.f;
    float acc[16];
    #pragma unroll
    for (int i = 0; i < 16; i++) acc[i] = 0.f;

    int kt_lo = max(0, qs - (MAXLEN - 1)) >> 5;
    int kt_hi = (qs + 63) >> 5;
    const float* rp = rel_pos + h * MAXLEN;
    int kb = quarter * 8;
    int dbase = quarter * 16;

    for (int kt = kt_lo; kt <= kt_hi; kt++) {
        int ks0 = kt * 32;
        __syncthreads();
        {
            int j = tid >> 3;
            int d0 = (tid & 7) * 8;
            const float* kp = base + (size_t)(ks0 + j) * 3 * E_ + E_ + h * DH + d0;
            const float* vp = base + (size_t)(ks0 + j) * 3 * E_ + 2 * E_ + h * DH + d0;
            float4 k0v = *(const float4*)kp;
            float4 k1v = *(const float4*)(kp + 4);
            Kt[d0 + 0][j] = k0v.x; Kt[d0 + 1][j] = k0v.y;
            Kt[d0 + 2][j] = k0v.z; Kt[d0 + 3][j] = k0v.w;
            Kt[d0 + 4][j] = k1v.x; Kt[d0 + 5][j] = k1v.y;
            Kt[d0 + 6][j] = k1v.z; Kt[d0 + 7][j] = k1v.w;
            *(float4*)&Vs[j][d0]     = *(const float4*)vp;
            *(float4*)&Vs[j][d0 + 4] = *(const float4*)(vp + 4);
        }
        __syncthreads();

        float s[8];
        #pragma unroll
        for (int i = 0; i < 8; i++) s[i] = 0.f;
        for (int d = 0; d < 64; d += 4) {
            float4 q4 = *(const float4*)&Qs[qrow][d];
            #pragma unroll
            for (int kk = 0; kk < 8; kk++) {
                s[kk] += q4.x * Kt[d + 0][kb + kk];
                s[kk] += q4.y * Kt[d + 1][kb + kk];
                s[kk] += q4.z * Kt[d + 2][kb + kk];
                s[kk] += q4.w * Kt[d + 3][kb + kk];
            }
        }
        float m_t = -INFINITY;
        #pragma unroll
        for (int kk = 0; kk < 8; kk++) {
            int j = ks0 + kb + kk;
            int rel = i_glob - j;
            if (rel >= 0 && rel < MAXLEN)
                s[kk] = s[kk] * 0.125f + __ldg(rp + rel);
            else
                s[kk] = -INFINITY;
            m_t = fmaxf(m_t, s[kk]);
        }
        m_t = fmaxf(m_t, __shfl_xor_sync(0xffffffffu, m_t, 1));
        m_t = fmaxf(m_t, __shfl_xor_sync(0xffffffffu, m_t, 2));
        float m_new = fmaxf(m_old, m_t);
        if (m_new == -INFINITY) {
            #pragma unroll
            for (int kk = 0; kk < 8; kk++) Ss[qrow][kb + kk] = 0.f;
        } else {
            float factor = __expf(m_old - m_new);
            float psum = 0.f;
            #pragma unroll
            for (int kk = 0; kk < 8; kk++) {
                float p = (s[kk] == -INFINITY) ? 0.f : __expf(s[kk] - m_new);
                Ss[qrow][kb + kk] = p;
                psum += p;
            }
            l = l * factor + psum;
            #pragma unroll
            for (int i = 0; i < 16; i++) acc[i] *= factor;
            m_old = m_new;
        }
        __syncthreads();
        #pragma unroll 4
        for (int k = 0; k < 32; k++) {
            float p = Ss[qrow][k];
            #pragma unroll
            for (int i = 0; i < 16; i += 4) {
                float4 v4 = *(const float4*)&Vs[k][dbase + i];
                acc[i + 0] += p * v4.x;
                acc[i + 1] += p * v4.y;
                acc[i + 2] += p * v4.z;
                acc[i + 3] += p * v4.w;
            }
        }
    }
    float lt = l;
    lt += __shfl_xor_sync(0xffffffffu, lt, 1);
    lt += __shfl_xor_sync(0xffffffffu, lt, 2);
    float inv = 1.f / lt;
    float* op = o + ((size_t)(b * N_ + i_glob)) * E_ + h * DH + dbase;
    #pragma unroll
    for (int i = 0; i < 16; i++) op[i] = acc[i] * inv;
}

// ---------------- driver ----------------
extern "C" void kernel_launch(void* const* d_in, const int* in_sizes, int n_in,
                              void* d_out, int out_size) {
    const float* x         = (const float*)d_in[0];
    const float* rel_pos   = (const float*)d_in[1];
    const float* in_proj_w = (const float*)d_in[2];
    const float* in_proj_b = (const float*)d_in[3];
    const float* out_w     = (const float*)d_in[4];
    const float* out_b     = (const float*)d_in[5];
    const float* w1        = (const float*)d_in[6];
    const float* b1        = (const float*)d_in[7];
    const float* w2        = (const float*)d_in[8];
    const float* b2        = (const float*)d_in[9];
    const float* ln1_g     = (const float*)d_in[10];
    const float* ln1_b     = (const float*)d_in[11];
    const float* ln2_g     = (const float*)d_in[12];
    const float* ln2_b     = (const float*)d_in[13];
    float* out = (float*)d_out;

    float *xn, *qkv, *o, *xm, *hbuf;
    cudaGetSymbolAddress((void**)&xn,   g_xn);
    cudaGetSymbolAddress((void**)&qkv,  g_qkv);
    cudaGetSymbolAddress((void**)&o,    g_o);
    cudaGetSymbolAddress((void**)&xm,   g_xm);
    cudaGetSymbolAddress((void**)&hbuf, g_hbuf);

    // 1) LN1
    ln_kernel<<<ROWS, 256>>>(x, ln1_g, ln1_b, xn);
    // 2) QKV = xn @ in_proj_w^T + b       [4096, 3072]
    gemm_tc<<<dim3(3 * E_ / 128, ROWS / 128), 128>>>(
        xn, in_proj_w, in_proj_b, nullptr, qkv, ROWS, 3 * E_, E_, 0);
    // 3) windowed attention -> o          [4096, 1024]
    attn_kernel<<<dim3(N_ / 64, H_, B_), 256>>>(qkv, rel_pos, o);
    // 4) x2 = x + o @ out_w^T + out_b  -> d_out
    gemm_tc<<<dim3(E_ / 128, ROWS / 128), 128>>>(
        o, out_w, out_b, x, out, ROWS, E_, E_, 0);
    // 5) LN2
    ln_kernel<<<ROWS, 256>>>(out, ln2_g, ln2_b, xm);
    // 6) h = relu(xm @ w1^T + b1)         [4096, 4096]
    gemm_tc<<<dim3(FF / 128, ROWS / 128), 128>>>(
        xm, w1, b1, nullptr, hbuf, ROWS, FF, E_, 1);
    // 7) out = x2 + h @ w2^T + b2
    gemm_tc<<<dim3(E_ / 128, ROWS / 128), 128>>>(
        hbuf, w2, b2, out, out, ROWS, E_, FF, 0);
}

// round 4
// speedup vs baseline: 3.4397x; 1.5100x over previous
#include <cuda_runtime.h>
#include <math.h>
#include <stdint.h>

#define E_    1024
#define H_    16
#define DH    64
#define B_    4
#define N_    1024
#define ROWS  (B_ * N_)      // 4096
#define FF    (4 * E_)       // 4096
#define MAXLEN 512

// ---------------- scratch (no allocs allowed) ----------------
__device__ float g_xn[ROWS * E_];
__device__ float g_qkv[ROWS * 3 * E_];
__device__ float g_o[ROWS * E_];
__device__ float g_xm[ROWS * E_];
__device__ float g_hbuf[ROWS * FF];

__device__ __forceinline__ uint32_t cvt_tf32(float f) {
    uint32_t r;
    asm("cvt.rna.tf32.f32 %0, %1;" : "=r"(r) : "f"(f));
    return r;
}

__device__ __forceinline__ void mma_tf32(float* c, const uint32_t* a, const uint32_t* b) {
    asm volatile(
        "mma.sync.aligned.m16n8k8.row.col.f32.tf32.tf32.f32 "
        "{%0,%1,%2,%3}, {%4,%5,%6,%7}, {%8,%9}, {%0,%1,%2,%3};"
        : "+f"(c[0]), "+f"(c[1]), "+f"(c[2]), "+f"(c[3])
        : "r"(a[0]), "r"(a[1]), "r"(a[2]), "r"(a[3]), "r"(b[0]), "r"(b[1]));
}

// ---------------- LayerNorm ----------------
__global__ void ln_kernel(const float* __restrict__ x, const float* __restrict__ g,
                          const float* __restrict__ bt, float* __restrict__ out) {
    int row = blockIdx.x;
    int tid = threadIdx.x;
    const float4* xr = (const float4*)(x + (size_t)row * E_);
    float4 v = xr[tid];
    float s  = v.x + v.y + v.z + v.w;
    float s2 = v.x*v.x + v.y*v.y + v.z*v.z + v.w*v.w;
    #pragma unroll
    for (int o = 16; o; o >>= 1) {
        s  += __shfl_xor_sync(0xffffffffu, s,  o);
        s2 += __shfl_xor_sync(0xffffffffu, s2, o);
    }
    __shared__ float ws[8], ws2[8];
    int w = tid >> 5;
    if ((tid & 31) == 0) { ws[w] = s; ws2[w] = s2; }
    __syncthreads();
    if (tid < 32) {
        float a  = (tid < 8) ? ws[tid]  : 0.f;
        float a2 = (tid < 8) ? ws2[tid] : 0.f;
        #pragma unroll
        for (int o = 4; o; o >>= 1) {
            a  += __shfl_xor_sync(0xffffffffu, a,  o);
            a2 += __shfl_xor_sync(0xffffffffu, a2, o);
        }
        if (tid == 0) {
            float mu  = a / (float)E_;
            float var = a2 / (float)E_ - mu * mu;
            ws[0]  = mu;
            ws2[0] = rsqrtf(var + 1e-5f);
        }
    }
    __syncthreads();
    float mu = ws[0], rstd = ws2[0];
    float4 gv = ((const float4*)g)[tid];
    float4 bv = ((const float4*)bt)[tid];
    float4 ov;
    ov.x = (v.x - mu) * rstd * gv.x + bv.x;
    ov.y = (v.y - mu) * rstd * gv.y + bv.y;
    ov.z = (v.z - mu) * rstd * gv.z + bv.z;
    ov.w = (v.w - mu) * rstd * gv.w + bv.w;
    ((float4*)(out + (size_t)row * E_))[tid] = ov;
}

// ---------------- tf32 mma GEMM: 128x128 block, 8 warps (4x2), 32x64 warp tile ----
#define BK  16
#define SST 20

__global__ void __launch_bounds__(256, 2)
gemm_tc(const float* __restrict__ A, const float* __restrict__ W,
        const float* __restrict__ bias, const float* __restrict__ res,
        float* __restrict__ C, int M, int Nn, int K, int relu) {
    __shared__ uint32_t SA[2][128 * SST];
    __shared__ uint32_t SB[2][128 * SST];

    int tid = threadIdx.x;
    int wid = tid >> 5, lane = tid & 31;
    int g = lane >> 2, t = lane & 3;
    int wm = wid >> 1, wn = wid & 1;              // 4x2 warp grid, 32x64 tiles
    int bm = blockIdx.y * 128, bn = blockIdx.x * 128;

    int lrow = tid >> 2, lc4 = tid & 3;           // lrow 0..63
    const float* Ag = A + (size_t)(bm + lrow) * K + lc4 * 4;
    const float* Wg = W + (size_t)(bn + lrow) * K + lc4 * 4;

    float acc[2][8][4];
    #pragma unroll
    for (int i = 0; i < 2; i++)
        #pragma unroll
        for (int j = 0; j < 8; j++)
            #pragma unroll
            for (int v = 0; v < 4; v++) acc[i][j][v] = 0.f;

    int S = K / BK;
    float4 pa[2], pb[2];
    #pragma unroll
    for (int i = 0; i < 2; i++) {
        pa[i] = *(const float4*)(Ag + (size_t)(i * 64) * K);
        pb[i] = *(const float4*)(Wg + (size_t)(i * 64) * K);
    }
    #pragma unroll
    for (int i = 0; i < 2; i++) {
        uint32_t* da = &SA[0][(lrow + i * 64) * SST + lc4 * 4];
        uint32_t* db = &SB[0][(lrow + i * 64) * SST + lc4 * 4];
        da[0] = cvt_tf32(pa[i].x); da[1] = cvt_tf32(pa[i].y);
        da[2] = cvt_tf32(pa[i].z); da[3] = cvt_tf32(pa[i].w);
        db[0] = cvt_tf32(pb[i].x); db[1] = cvt_tf32(pb[i].y);
        db[2] = cvt_tf32(pb[i].z); db[3] = cvt_tf32(pb[i].w);
    }
    __syncthreads();

    for (int s = 0; s < S; s++) {
        int cur = s & 1;
        if (s + 1 < S) {
            const float* Ag2 = Ag + (size_t)(s + 1) * BK;
            const float* Wg2 = Wg + (size_t)(s + 1) * BK;
            #pragma unroll
            for (int i = 0; i < 2; i++) {
                pa[i] = *(const float4*)(Ag2 + (size_t)(i * 64) * K);
                pb[i] = *(const float4*)(Wg2 + (size_t)(i * 64) * K);
            }
        }
        #pragma unroll
        for (int ks = 0; ks < 2; ks++) {
            int ko = ks * 8 + t;
            uint32_t af[2][4];
            #pragma unroll
            for (int mi = 0; mi < 2; mi++) {
                int r0 = wm * 32 + mi * 16 + g;
                af[mi][0] = SA[cur][r0 * SST + ko];
                af[mi][1] = SA[cur][(r0 + 8) * SST + ko];
                af[mi][2] = SA[cur][r0 * SST + ko + 4];
                af[mi][3] = SA[cur][(r0 + 8) * SST + ko + 4];
            }
            uint32_t bf[8][2];
            #pragma unroll
            for (int ni = 0; ni < 8; ni++) {
                int rn = wn * 64 + ni * 8 + g;
                bf[ni][0] = SB[cur][rn * SST + ko];
                bf[ni][1] = SB[cur][rn * SST + ko + 4];
            }
            #pragma unroll
            for (int mi = 0; mi < 2; mi++)
                #pragma unroll
                for (int ni = 0; ni < 8; ni++)
                    mma_tf32(acc[mi][ni], af[mi], bf[ni]);
        }
        if (s + 1 < S) {
            int nxt = cur ^ 1;
            #pragma unroll
            for (int i = 0; i < 2; i++) {
                uint32_t* da = &SA[nxt][(lrow + i * 64) * SST + lc4 * 4];
                uint32_t* db = &SB[nxt][(lrow + i * 64) * SST + lc4 * 4];
                da[0] = cvt_tf32(pa[i].x); da[1] = cvt_tf32(pa[i].y);
                da[2] = cvt_tf32(pa[i].z); da[3] = cvt_tf32(pa[i].w);
                db[0] = cvt_tf32(pb[i].x); db[1] = cvt_tf32(pb[i].y);
                db[2] = cvt_tf32(pb[i].z); db[3] = cvt_tf32(pb[i].w);
            }
            __syncthreads();
        }
    }

    #pragma unroll
    for (int mi = 0; mi < 2; mi++) {
        int r0 = bm + wm * 32 + mi * 16 + g;
        #pragma unroll
        for (int half = 0; half < 2; half++) {
            int row = r0 + half * 8;
            float* crow = C + (size_t)row * Nn + bn + wn * 64;
            const float* rrow = res ? res + (size_t)row * Nn + bn + wn * 64 : nullptr;
            const float* brow = bias + bn + wn * 64;
            #pragma unroll
            for (int ni = 0; ni < 8; ni++) {
                int col = ni * 8 + 2 * t;
                float v0 = acc[mi][ni][half * 2 + 0] + brow[col];
                float v1 = acc[mi][ni][half * 2 + 1] + brow[col + 1];
                if (relu) { v0 = fmaxf(v0, 0.f); v1 = fmaxf(v1, 0.f); }
                if (rrow) { v0 += rrow[col]; v1 += rrow[col + 1]; }
                *(float2*)(crow + col) = make_float2(v0, v1);
            }
        }
    }
}

// ---------------- Tensor-core windowed attention ------------------------------
// 128 q-rows per block, 8 warps x 16 rows, key tiles of 32, online softmax on
// mma fragments. Q fragments live in registers for the whole block.
__global__ void __launch_bounds__(256)
attn_kernel(const float* __restrict__ qkv, const float* __restrict__ rel_pos,
            float* __restrict__ o) {
    __shared__ uint32_t Ks[32][68];   // [key][d]   bank: 4g+t  (stride%32==4)
    __shared__ uint32_t Vs[32][72];   // [key][d]   bank: 8t+g  (stride%32==8)
    __shared__ uint32_t Ps[128][36];  // [qrow][key] bank: 4g+t

    int tid = threadIdx.x;
    int wid = tid >> 5, lane = tid & 31;
    int g = lane >> 2, t = lane & 3;
    int b = blockIdx.z, h = blockIdx.y;
    int qs = blockIdx.x * 128;
    const float* base = qkv + (size_t)b * N_ * 3 * E_;
    const float* rp = rel_pos + h * MAXLEN;

    int row0 = qs + wid * 16 + g;         // this thread's rows: row0, row0+8
    // ---- Q fragments in registers (prescaled by 1/8, tf32-rounded) ----
    uint32_t qf[8][4];
    {
        const float* q0 = base + (size_t)row0 * 3 * E_ + h * DH;
        const float* q1 = q0 + (size_t)8 * 3 * E_;
        #pragma unroll
        for (int kk = 0; kk < 8; kk++) {
            qf[kk][0] = cvt_tf32(0.125f * q0[kk * 8 + t]);
            qf[kk][1] = cvt_tf32(0.125f * q1[kk * 8 + t]);
            qf[kk][2] = cvt_tf32(0.125f * q0[kk * 8 + t + 4]);
            qf[kk][3] = cvt_tf32(0.125f * q1[kk * 8 + t + 4]);
        }
    }

    float oacc[8][4];
    #pragma unroll
    for (int i = 0; i < 8; i++)
        #pragma unroll
        for (int v = 0; v < 4; v++) oacc[i][v] = 0.f;
    float m_o[2] = {-INFINITY, -INFINITY};
    float lac[2] = {0.f, 0.f};

    int kt_lo = max(0, qs - (MAXLEN - 1)) >> 5;
    int kt_hi = (qs + 127) >> 5;

    int jrow = tid >> 3;          // 0..31 key row for loads
    int d0 = (tid & 7) * 8;

    for (int kt = kt_lo; kt <= kt_hi; kt++) {
        int ks0 = kt * 32;
        __syncthreads();
        {
            const float* kp = base + (size_t)(ks0 + jrow) * 3 * E_ + E_ + h * DH + d0;
            const float* vp = kp + E_;
            float4 k0 = *(const float4*)kp,      k1 = *(const float4*)(kp + 4);
            float4 v0 = *(const float4*)vp,      v1 = *(const float4*)(vp + 4);
            Ks[jrow][d0 + 0] = cvt_tf32(k0.x); Ks[jrow][d0 + 1] = cvt_tf32(k0.y);
            Ks[jrow][d0 + 2] = cvt_tf32(k0.z); Ks[jrow][d0 + 3] = cvt_tf32(k0.w);
            Ks[jrow][d0 + 4] = cvt_tf32(k1.x); Ks[jrow][d0 + 5] = cvt_tf32(k1.y);
            Ks[jrow][d0 + 6] = cvt_tf32(k1.z); Ks[jrow][d0 + 7] = cvt_tf32(k1.w);
            Vs[jrow][d0 + 0] = cvt_tf32(v0.x); Vs[jrow][d0 + 1] = cvt_tf32(v0.y);
            Vs[jrow][d0 + 2] = cvt_tf32(v0.z); Vs[jrow][d0 + 3] = cvt_tf32(v0.w);
            Vs[jrow][d0 + 4] = cvt_tf32(v1.x); Vs[jrow][d0 + 5] = cvt_tf32(v1.y);
            Vs[jrow][d0 + 6] = cvt_tf32(v1.z); Vs[jrow][d0 + 7] = cvt_tf32(v1.w);
        }
        __syncthreads();

        // ---- S = (Q/8) K^T  (16x32 per warp) ----
        float sacc[4][4];
        #pragma unroll
        for (int ni = 0; ni < 4; ni++)
            #pragma unroll
            for (int v = 0; v < 4; v++) sacc[ni][v] = 0.f;
        #pragma unroll
        for (int kk = 0; kk < 8; kk++) {
            int ko = kk * 8 + t;   // not used directly; fragment k = t within group
            (void)ko;
            uint32_t bf[4][2];
            #pragma unroll
            for (int ni = 0; ni < 4; ni++) {
                int rn = ni * 8 + g;
                bf[ni][0] = Ks[rn][kk * 8 + t];
                bf[ni][1] = Ks[rn][kk * 8 + t + 4];
            }
            #pragma unroll
            for (int ni = 0; ni < 4; ni++)
                mma_tf32(sacc[ni], qf[kk], bf[ni]);
        }

        // ---- bias + window mask + online softmax (2 rows per thread) ----
        float m_t[2] = {-INFINITY, -INFINITY};
        #pragma unroll
        for (int ni = 0; ni < 4; ni++) {
            #pragma unroll
            for (int v = 0; v < 4; v++) {
                int r = v >> 1;                       // 0: row0, 1: row0+8
                int i_glob = row0 + r * 8;
                int j = ks0 + ni * 8 + 2 * t + (v & 1);
                int rel = i_glob - j;
                float val;
                if (rel >= 0 && rel < MAXLEN) val = sacc[ni][v] + __ldg(rp + rel);
                else                          val = -INFINITY;
                sacc[ni][v] = val;
                m_t[r] = fmaxf(m_t[r], val);
            }
        }
        #pragma unroll
        for (int r = 0; r < 2; r++) {
            m_t[r] = fmaxf(m_t[r], __shfl_xor_sync(0xffffffffu, m_t[r], 1));
            m_t[r] = fmaxf(m_t[r], __shfl_xor_sync(0xffffffffu, m_t[r], 2));
        }
        float fac[2], m_n[2];
        #pragma unroll
        for (int r = 0; r < 2; r++) {
            m_n[r] = fmaxf(m_o[r], m_t[r]);
            fac[r] = (m_n[r] == -INFINITY) ? 1.f : __expf(m_o[r] - m_n[r]);
            if (m_o[r] == -INFINITY) fac[r] = 0.f;
            if (m_n[r] == -INFINITY) fac[r] = 1.f;
        }
        float psum[2] = {0.f, 0.f};
        int lrow0 = wid * 16 + g;
        #pragma unroll
        for (int ni = 0; ni < 4; ni++) {
            #pragma unroll
            for (int v = 0; v < 4; v++) {
                int r = v >> 1;
                float p = (m_n[r] == -INFINITY) ? 0.f : __expf(sacc[ni][v] - m_n[r]);
                psum[r] += p;
                Ps[lrow0 + r * 8][ni * 8 + 2 * t + (v & 1)] = cvt_tf32(p);
            }
        }
        #pragma unroll
        for (int r = 0; r < 2; r++) {
            psum[r] += __shfl_xor_sync(0xffffffffu, psum[r], 1);
            psum[r] += __shfl_xor_sync(0xffffffffu, psum[r], 2);
            lac[r] = lac[r] * fac[r] + psum[r];
            m_o[r] = m_n[r];
        }
        #pragma unroll
        for (int i = 0; i < 8; i++) {
            oacc[i][0] *= fac[0]; oacc[i][1] *= fac[0];
            oacc[i][2] *= fac[1]; oacc[i][3] *= fac[1];
        }
        __syncwarp();

        // ---- O += P V  (16x64 per warp, k=32) ----
        #pragma unroll
        for (int kk = 0; kk < 4; kk++) {
            uint32_t af[4];
            af[0] = Ps[lrow0][kk * 8 + t];
            af[1] = Ps[lrow0 + 8][kk * 8 + t];
            af[2] = Ps[lrow0][kk * 8 + t + 4];
            af[3] = Ps[lrow0 + 8][kk * 8 + t + 4];
            #pragma unroll
            for (int ni = 0; ni < 8; ni++) {
                uint32_t bf[2];
                bf[0] = Vs[kk * 8 + t][ni * 8 + g];
                bf[1] = Vs[kk * 8 + t + 4][ni * 8 + g];
                mma_tf32(oacc[ni], af, bf);
            }
        }
        __syncwarp();
    }

    // ---- epilogue ----
    float inv0 = 1.f / lac[0];
    float inv1 = 1.f / lac[1];
    float* op0 = o + ((size_t)(b * N_) + row0) * E_ + h * DH;
    float* op1 = op0 + (size_t)8 * E_;
    #pragma unroll
    for (int ni = 0; ni < 8; ni++) {
        int col = ni * 8 + 2 * t;
        *(float2*)(op0 + col) = make_float2(oacc[ni][0] * inv0, oacc[ni][1] * inv0);
        *(float2*)(op1 + col) = make_float2(oacc[ni][2] * inv1, oacc[ni][3] * inv1);
    }
}

// ---------------- driver ----------------
extern "C" void kernel_launch(void* const* d_in, const int* in_sizes, int n_in,
                              void* d_out, int out_size) {
    const float* x         = (const float*)d_in[0];
    const float* rel_pos   = (const float*)d_in[1];
    const float* in_proj_w = (const float*)d_in[2];
    const float* in_proj_b = (const float*)d_in[3];
    const float* out_w     = (const float*)d_in[4];
    const float* out_b     = (const float*)d_in[5];
    const float* w1        = (const float*)d_in[6];
    const float* b1        = (const float*)d_in[7];
    const float* w2        = (const float*)d_in[8];
    const float* b2        = (const float*)d_in[9];
    const float* ln1_g     = (const float*)d_in[10];
    const float* ln1_b     = (const float*)d_in[11];
    const float* ln2_g     = (const float*)d_in[12];
    const float* ln2_b     = (const float*)d_in[13];
    float* out = (float*)d_out;

    float *xn, *qkv, *o, *xm, *hbuf;
    cudaGetSymbolAddress((void**)&xn,   g_xn);
    cudaGetSymbolAddress((void**)&qkv,  g_qkv);
    cudaGetSymbolAddress((void**)&o,    g_o);
    cudaGetSymbolAddress((void**)&xm,   g_xm);
    cudaGetSymbolAddress((void**)&hbuf, g_hbuf);

    ln_kernel<<<ROWS, 256>>>(x, ln1_g, ln1_b, xn);
    gemm_tc<<<dim3(3 * E_ / 128, ROWS / 128), 256>>>(
        xn, in_proj_w, in_proj_b, nullptr, qkv, ROWS, 3 * E_, E_, 0);
    attn_kernel<<<dim3(N_ / 128, H_, B_), 256>>>(qkv, rel_pos, o);
    gemm_tc<<<dim3(E_ / 128, ROWS / 128), 256>>>(
        o, out_w, out_b, x, out, ROWS, E_, E_, 0);
    ln_kernel<<<ROWS, 256>>>(out, ln2_g, ln2_b, xm);
    gemm_tc<<<dim3(FF / 128, ROWS / 128), 256>>>(
        xm, w1, b1, nullptr, hbuf, ROWS, FF, E_, 1);
    gemm_tc<<<dim3(E_ / 128, ROWS / 128), 256>>>(
        hbuf, w2, b2, out, out, ROWS, E_, FF, 0);
}

// round 5
// speedup vs baseline: 3.8446x; 1.1177x over previous
#include <cuda_runtime.h>
#include <math.h>
#include <stdint.h>

#define E_    1024
#define H_    16
#define DH    64
#define B_    4
#define N_    1024
#define ROWS  (B_ * N_)      // 4096
#define FF    (4 * E_)       // 4096
#define MAXLEN 512

// ---------------- scratch (no allocs allowed) ----------------
__device__ float g_xn[ROWS * E_];
__device__ float g_qkv[ROWS * 3 * E_];
__device__ float g_o[ROWS * E_];
__device__ float g_xm[ROWS * E_];
__device__ float g_hbuf[ROWS * FF];
// tf32-pre-rounded weights
__device__ float g_wqkv[3 * E_ * E_];
__device__ float g_wout[E_ * E_];
__device__ float g_w1[FF * E_];
__device__ float g_w2[E_ * FF];

__device__ __forceinline__ uint32_t cvt_tf32(float f) {
    uint32_t r;
    asm("cvt.rna.tf32.f32 %0, %1;" : "=r"(r) : "f"(f));
    return r;
}

__device__ __forceinline__ void mma_tf32(float* c, const uint32_t* a, const uint32_t* b) {
    asm volatile(
        "mma.sync.aligned.m16n8k8.row.col.f32.tf32.tf32.f32 "
        "{%0,%1,%2,%3}, {%4,%5,%6,%7}, {%8,%9}, {%0,%1,%2,%3};"
        : "+f"(c[0]), "+f"(c[1]), "+f"(c[2]), "+f"(c[3])
        : "r"(a[0]), "r"(a[1]), "r"(a[2]), "r"(a[3]), "r"(b[0]), "r"(b[1]));
}

__device__ __forceinline__ void cp16(uint32_t smem_addr, const void* gptr) {
    asm volatile("cp.async.cg.shared.global [%0], [%1], 16;"
                 :: "r"(smem_addr), "l"(gptr) : "memory");
}
#define CP_COMMIT() asm volatile("cp.async.commit_group;" ::: "memory")
#define CP_WAIT2()  asm volatile("cp.async.wait_group 2;" ::: "memory")

// ---------------- weight rounding ----------------
__global__ void round_kernel(const float* __restrict__ in, float* __restrict__ out) {
    int i = (blockIdx.x * blockDim.x + threadIdx.x) * 4;
    float4 v = *(const float4*)(in + i);
    uint4 o;
    o.x = cvt_tf32(v.x); o.y = cvt_tf32(v.y);
    o.z = cvt_tf32(v.z); o.w = cvt_tf32(v.w);
    *(uint4*)(out + i) = o;
}

// ---------------- LayerNorm (emits tf32-rounded output) ----------------
__global__ void ln_kernel(const float* __restrict__ x, const float* __restrict__ g,
                          const float* __restrict__ bt, float* __restrict__ out) {
    int row = blockIdx.x;
    int tid = threadIdx.x;
    const float4* xr = (const float4*)(x + (size_t)row * E_);
    float4 v = xr[tid];
    float s  = v.x + v.y + v.z + v.w;
    float s2 = v.x*v.x + v.y*v.y + v.z*v.z + v.w*v.w;
    #pragma unroll
    for (int o = 16; o; o >>= 1) {
        s  += __shfl_xor_sync(0xffffffffu, s,  o);
        s2 += __shfl_xor_sync(0xffffffffu, s2, o);
    }
    __shared__ float ws[8], ws2[8];
    int w = tid >> 5;
    if ((tid & 31) == 0) { ws[w] = s; ws2[w] = s2; }
    __syncthreads();
    if (tid < 32) {
        float a  = (tid < 8) ? ws[tid]  : 0.f;
        float a2 = (tid < 8) ? ws2[tid] : 0.f;
        #pragma unroll
        for (int o = 4; o; o >>= 1) {
            a  += __shfl_xor_sync(0xffffffffu, a,  o);
            a2 += __shfl_xor_sync(0xffffffffu, a2, o);
        }
        if (tid == 0) {
            float mu  = a / (float)E_;
            float var = a2 / (float)E_ - mu * mu;
            ws[0]  = mu;
            ws2[0] = rsqrtf(var + 1e-5f);
        }
    }
    __syncthreads();
    float mu = ws[0], rstd = ws2[0];
    float4 gv = ((const float4*)g)[tid];
    float4 bv = ((const float4*)bt)[tid];
    uint4 ov;
    ov.x = cvt_tf32((v.x - mu) * rstd * gv.x + bv.x);
    ov.y = cvt_tf32((v.y - mu) * rstd * gv.y + bv.y);
    ov.z = cvt_tf32((v.z - mu) * rstd * gv.z + bv.z);
    ov.w = cvt_tf32((v.w - mu) * rstd * gv.w + bv.w);
    ((uint4*)(out + (size_t)row * E_))[tid] = ov;
}

// ---------------- tf32 GEMM: 128x128 block, 4 warps (2x2), 64x64 warp tile ----
// 4-stage cp.async pipeline, BK=16. Operands must be pre-rounded to tf32.
#define BK      16
#define SST     20
#define STAGES  4
#define STAGE_ELTS (128 * SST)
#define GSMEM_BYTES (STAGES * STAGE_ELTS * 2 * 4)

__global__ void __launch_bounds__(128, 2)
gemm_tc(const float* __restrict__ A, const float* __restrict__ W,
        const float* __restrict__ bias, const float* __restrict__ res,
        float* __restrict__ C, int M, int Nn, int K, int relu, int round_out) {
    extern __shared__ float smem[];
    float* SA = smem;
    float* SB = smem + STAGES * STAGE_ELTS;
    uint32_t sa_u = (uint32_t)__cvta_generic_to_shared(SA);
    uint32_t sb_u = (uint32_t)__cvta_generic_to_shared(SB);

    int tid = threadIdx.x;
    int wid = tid >> 5, lane = tid & 31;
    int g = lane >> 2, t = lane & 3;
    int wm = wid >> 1, wn = wid & 1;
    int bm = blockIdx.y * 128, bn = blockIdx.x * 128;

    int lrow = tid >> 2, lc4 = tid & 3;   // lrow 0..31, 4 row-chunks of 32
    const float* Ag = A + (size_t)(bm + lrow) * K + lc4 * 4;
    const float* Wg = W + (size_t)(bn + lrow) * K + lc4 * 4;
    uint32_t soff = (uint32_t)((lrow * SST + lc4 * 4) * 4);

    float acc[4][8][4];
    #pragma unroll
    for (int i = 0; i < 4; i++)
        #pragma unroll
        for (int j = 0; j < 8; j++)
            #pragma unroll
            for (int v = 0; v < 4; v++) acc[i][j][v] = 0.f;

    int S = K / BK;

    // issue stage s
    auto issue = [&](int s) {
        int st = s & (STAGES - 1);
        int koff = s * BK;
        uint32_t sbase = (uint32_t)(st * STAGE_ELTS * 4) + soff;
        #pragma unroll
        for (int i = 0; i < 4; i++) {
            cp16(sa_u + sbase + i * 32 * SST * 4, Ag + (size_t)i * 32 * K + koff);
            cp16(sb_u + sbase + i * 32 * SST * 4, Wg + (size_t)i * 32 * K + koff);
        }
        CP_COMMIT();
    };

    issue(0); issue(1); issue(2);

    for (int s = 0; s < S; s++) {
        CP_WAIT2();
        __syncthreads();
        if (s + 3 < S) issue(s + 3);
        else CP_COMMIT();

        int st = s & (STAGES - 1);
        const uint32_t* sa = (const uint32_t*)(SA + st * STAGE_ELTS);
        const uint32_t* sb = (const uint32_t*)(SB + st * STAGE_ELTS);
        #pragma unroll
        for (int ks = 0; ks < 2; ks++) {
            int ko = ks * 8 + t;
            uint32_t af[4][4];
            #pragma unroll
            for (int mi = 0; mi < 4; mi++) {
                int r0 = wm * 64 + mi * 16 + g;
                af[mi][0] = sa[r0 * SST + ko];
                af[mi][1] = sa[(r0 + 8) * SST + ko];
                af[mi][2] = sa[r0 * SST + ko + 4];
                af[mi][3] = sa[(r0 + 8) * SST + ko + 4];
            }
            uint32_t bf[8][2];
            #pragma unroll
            for (int ni = 0; ni < 8; ni++) {
                int rn = wn * 64 + ni * 8 + g;
                bf[ni][0] = sb[rn * SST + ko];
                bf[ni][1] = sb[rn * SST + ko + 4];
            }
            #pragma unroll
            for (int mi = 0; mi < 4; mi++)
                #pragma unroll
                for (int ni = 0; ni < 8; ni++)
                    mma_tf32(acc[mi][ni], af[mi], bf[ni]);
        }
    }

    // epilogue
    #pragma unroll
    for (int mi = 0; mi < 4; mi++) {
        int r0 = bm + wm * 64 + mi * 16 + g;
        #pragma unroll
        for (int half = 0; half < 2; half++) {
            int row = r0 + half * 8;
            float* crow = C + (size_t)row * Nn + bn + wn * 64;
            const float* rrow = res ? res + (size_t)row * Nn + bn + wn * 64 : nullptr;
            const float* brow = bias + bn + wn * 64;
            #pragma unroll
            for (int ni = 0; ni < 8; ni++) {
                int col = ni * 8 + 2 * t;
                float v0 = acc[mi][ni][half * 2 + 0] + brow[col];
                float v1 = acc[mi][ni][half * 2 + 1] + brow[col + 1];
                if (relu) { v0 = fmaxf(v0, 0.f); v1 = fmaxf(v1, 0.f); }
                if (rrow) { v0 += rrow[col]; v1 += rrow[col + 1]; }
                if (round_out) {
                    uint2 u = make_uint2(cvt_tf32(v0), cvt_tf32(v1));
                    *(uint2*)(crow + col) = u;
                } else {
                    *(float2*)(crow + col) = make_float2(v0, v1);
                }
            }
        }
    }
}

// ---------------- Tensor-core windowed attention (emits rounded o) -----------
__global__ void __launch_bounds__(256)
attn_kernel(const float* __restrict__ qkv, const float* __restrict__ rel_pos,
            float* __restrict__ o) {
    __shared__ uint32_t Ks[32][68];
    __shared__ uint32_t Vs[32][72];
    __shared__ uint32_t Ps[128][36];

    int tid = threadIdx.x;
    int wid = tid >> 5, lane = tid & 31;
    int g = lane >> 2, t = lane & 3;
    int b = blockIdx.z, h = blockIdx.y;
    int qs = blockIdx.x * 128;
    const float* base = qkv + (size_t)b * N_ * 3 * E_;
    const float* rp = rel_pos + h * MAXLEN;

    int row0 = qs + wid * 16 + g;
    uint32_t qf[8][4];
    {
        const float* q0 = base + (size_t)row0 * 3 * E_ + h * DH;
        const float* q1 = q0 + (size_t)8 * 3 * E_;
        #pragma unroll
        for (int kk = 0; kk < 8; kk++) {
            qf[kk][0] = cvt_tf32(0.125f * q0[kk * 8 + t]);
            qf[kk][1] = cvt_tf32(0.125f * q1[kk * 8 + t]);
            qf[kk][2] = cvt_tf32(0.125f * q0[kk * 8 + t + 4]);
            qf[kk][3] = cvt_tf32(0.125f * q1[kk * 8 + t + 4]);
        }
    }

    float oacc[8][4];
    #pragma unroll
    for (int i = 0; i < 8; i++)
        #pragma unroll
        for (int v = 0; v < 4; v++) oacc[i][v] = 0.f;
    float m_o[2] = {-INFINITY, -INFINITY};
    float lac[2] = {0.f, 0.f};

    int kt_lo = max(0, qs - (MAXLEN - 1)) >> 5;
    int kt_hi = (qs + 127) >> 5;

    int jrow = tid >> 3;
    int d0 = (tid & 7) * 8;

    for (int kt = kt_lo; kt <= kt_hi; kt++) {
        int ks0 = kt * 32;
        __syncthreads();
        {
            const float* kp = base + (size_t)(ks0 + jrow) * 3 * E_ + E_ + h * DH + d0;
            const float* vp = kp + E_;
            float4 k0 = *(const float4*)kp,      k1 = *(const float4*)(kp + 4);
            float4 v0 = *(const float4*)vp,      v1 = *(const float4*)(vp + 4);
            Ks[jrow][d0 + 0] = cvt_tf32(k0.x); Ks[jrow][d0 + 1] = cvt_tf32(k0.y);
            Ks[jrow][d0 + 2] = cvt_tf32(k0.z); Ks[jrow][d0 + 3] = cvt_tf32(k0.w);
            Ks[jrow][d0 + 4] = cvt_tf32(k1.x); Ks[jrow][d0 + 5] = cvt_tf32(k1.y);
            Ks[jrow][d0 + 6] = cvt_tf32(k1.z); Ks[jrow][d0 + 7] = cvt_tf32(k1.w);
            Vs[jrow][d0 + 0] = cvt_tf32(v0.x); Vs[jrow][d0 + 1] = cvt_tf32(v0.y);
            Vs[jrow][d0 + 2] = cvt_tf32(v0.z); Vs[jrow][d0 + 3] = cvt_tf32(v0.w);
            Vs[jrow][d0 + 4] = cvt_tf32(v1.x); Vs[jrow][d0 + 5] = cvt_tf32(v1.y);
            Vs[jrow][d0 + 6] = cvt_tf32(v1.z); Vs[jrow][d0 + 7] = cvt_tf32(v1.w);
        }
        __syncthreads();

        float sacc[4][4];
        #pragma unroll
        for (int ni = 0; ni < 4; ni++)
            #pragma unroll
            for (int v = 0; v < 4; v++) sacc[ni][v] = 0.f;
        #pragma unroll
        for (int kk = 0; kk < 8; kk++) {
            uint32_t bf[4][2];
            #pragma unroll
            for (int ni = 0; ni < 4; ni++) {
                int rn = ni * 8 + g;
                bf[ni][0] = Ks[rn][kk * 8 + t];
                bf[ni][1] = Ks[rn][kk * 8 + t + 4];
            }
            #pragma unroll
            for (int ni = 0; ni < 4; ni++)
                mma_tf32(sacc[ni], qf[kk], bf[ni]);
        }

        float m_t[2] = {-INFINITY, -INFINITY};
        #pragma unroll
        for (int ni = 0; ni < 4; ni++) {
            #pragma unroll
            for (int v = 0; v < 4; v++) {
                int r = v >> 1;
                int i_glob = row0 + r * 8;
                int j = ks0 + ni * 8 + 2 * t + (v & 1);
                int rel = i_glob - j;
                float val;
                if (rel >= 0 && rel < MAXLEN) val = sacc[ni][v] + __ldg(rp + rel);
                else                          val = -INFINITY;
                sacc[ni][v] = val;
                m_t[r] = fmaxf(m_t[r], val);
            }
        }
        #pragma unroll
        for (int r = 0; r < 2; r++) {
            m_t[r] = fmaxf(m_t[r], __shfl_xor_sync(0xffffffffu, m_t[r], 1));
            m_t[r] = fmaxf(m_t[r], __shfl_xor_sync(0xffffffffu, m_t[r], 2));
        }
        float fac[2], m_n[2];
        #pragma unroll
        for (int r = 0; r < 2; r++) {
            m_n[r] = fmaxf(m_o[r], m_t[r]);
            fac[r] = (m_n[r] == -INFINITY) ? 1.f : __expf(m_o[r] - m_n[r]);
            if (m_o[r] == -INFINITY) fac[r] = 0.f;
            if (m_n[r] == -INFINITY) fac[r] = 1.f;
        }
        float psum[2] = {0.f, 0.f};
        int lrow0 = wid * 16 + g;
        #pragma unroll
        for (int ni = 0; ni < 4; ni++) {
            #pragma unroll
            for (int v = 0; v < 4; v++) {
                int r = v >> 1;
                float p = (m_n[r] == -INFINITY) ? 0.f : __expf(sacc[ni][v] - m_n[r]);
                psum[r] += p;
                Ps[lrow0 + r * 8][ni * 8 + 2 * t + (v & 1)] = cvt_tf32(p);
            }
        }
        #pragma unroll
        for (int r = 0; r < 2; r++) {
            psum[r] += __shfl_xor_sync(0xffffffffu, psum[r], 1);
            psum[r] += __shfl_xor_sync(0xffffffffu, psum[r], 2);
            lac[r] = lac[r] * fac[r] + psum[r];
            m_o[r] = m_n[r];
        }
        #pragma unroll
        for (int i = 0; i < 8; i++) {
            oacc[i][0] *= fac[0]; oacc[i][1] *= fac[0];
            oacc[i][2] *= fac[1]; oacc[i][3] *= fac[1];
        }
        __syncwarp();

        #pragma unroll
        for (int kk = 0; kk < 4; kk++) {
            uint32_t af[4];
            af[0] = Ps[lrow0][kk * 8 + t];
            af[1] = Ps[lrow0 + 8][kk * 8 + t];
            af[2] = Ps[lrow0][kk * 8 + t + 4];
            af[3] = Ps[lrow0 + 8][kk * 8 + t + 4];
            #pragma unroll
            for (int ni = 0; ni < 8; ni++) {
                uint32_t bf[2];
                bf[0] = Vs[kk * 8 + t][ni * 8 + g];
                bf[1] = Vs[kk * 8 + t + 4][ni * 8 + g];
                mma_tf32(oacc[ni], af, bf);
            }
        }
        __syncwarp();
    }

    float inv0 = 1.f / lac[0];
    float inv1 = 1.f / lac[1];
    float* op0 = o + ((size_t)(b * N_) + row0) * E_ + h * DH;
    float* op1 = op0 + (size_t)8 * E_;
    #pragma unroll
    for (int ni = 0; ni < 8; ni++) {
        int col = ni * 8 + 2 * t;
        uint2 u0 = make_uint2(cvt_tf32(oacc[ni][0] * inv0), cvt_tf32(oacc[ni][1] * inv0));
        uint2 u1 = make_uint2(cvt_tf32(oacc[ni][2] * inv1), cvt_tf32(oacc[ni][3] * inv1));
        *(uint2*)(op0 + col) = u0;
        *(uint2*)(op1 + col) = u1;
    }
}

// ---------------- driver ----------------
extern "C" void kernel_launch(void* const* d_in, const int* in_sizes, int n_in,
                              void* d_out, int out_size) {
    const float* x         = (const float*)d_in[0];
    const float* rel_pos   = (const float*)d_in[1];
    const float* in_proj_w = (const float*)d_in[2];
    const float* in_proj_b = (const float*)d_in[3];
    const float* out_w     = (const float*)d_in[4];
    const float* out_b     = (const float*)d_in[5];
    const float* w1        = (const float*)d_in[6];
    const float* b1        = (const float*)d_in[7];
    const float* w2        = (const float*)d_in[8];
    const float* b2        = (const float*)d_in[9];
    const float* ln1_g     = (const float*)d_in[10];
    const float* ln1_b     = (const float*)d_in[11];
    const float* ln2_g     = (const float*)d_in[12];
    const float* ln2_b     = (const float*)d_in[13];
    float* out = (float*)d_out;

    float *xn, *qkv, *o, *xm, *hbuf, *wqkv, *wout, *w1r, *w2r;
    cudaGetSymbolAddress((void**)&xn,   g_xn);
    cudaGetSymbolAddress((void**)&qkv,  g_qkv);
    cudaGetSymbolAddress((void**)&o,    g_o);
    cudaGetSymbolAddress((void**)&xm,   g_xm);
    cudaGetSymbolAddress((void**)&hbuf, g_hbuf);
    cudaGetSymbolAddress((void**)&wqkv, g_wqkv);
    cudaGetSymbolAddress((void**)&wout, g_wout);
    cudaGetSymbolAddress((void**)&w1r,  g_w1);
    cudaGetSymbolAddress((void**)&w2r,  g_w2);

    static int smem_set = 0;
    if (!smem_set) {
        cudaFuncSetAttribute(gemm_tc, cudaFuncAttributeMaxDynamicSharedMemorySize,
                             GSMEM_BYTES);
        smem_set = 1;
    }

    // weight pre-rounding (tf32 rna)
    round_kernel<<<3 * E_ * E_ / 1024, 256>>>(in_proj_w, wqkv);
    round_kernel<<<E_ * E_ / 1024, 256>>>(out_w, wout);
    round_kernel<<<FF * E_ / 1024, 256>>>(w1, w1r);
    round_kernel<<<E_ * FF / 1024, 256>>>(w2, w2r);

    ln_kernel<<<ROWS, 256>>>(x, ln1_g, ln1_b, xn);
    gemm_tc<<<dim3(3 * E_ / 128, ROWS / 128), 128, GSMEM_BYTES>>>(
        xn, wqkv, in_proj_b, nullptr, qkv, ROWS, 3 * E_, E_, 0, 0);
    attn_kernel<<<dim3(N_ / 128, H_, B_), 256>>>(qkv, rel_pos, o);
    gemm_tc<<<dim3(E_ / 128, ROWS / 128), 128, GSMEM_BYTES>>>(
        o, wout, out_b, x, out, ROWS, E_, E_, 0, 0);
    ln_kernel<<<ROWS, 256>>>(out, ln2_g, ln2_b, xm);
    gemm_tc<<<dim3(FF / 128, ROWS / 128), 128, GSMEM_BYTES>>>(
        xm, w1r, b1, nullptr, hbuf, ROWS, FF, E_, 1, 1);
    gemm_tc<<<dim3(E_ / 128, ROWS / 128), 128, GSMEM_BYTES>>>(
        hbuf, w2r, b2, out, out, ROWS, E_, FF, 0, 0);
}